// round 5
// baseline (speedup 1.0000x reference)
#include <cuda_runtime.h>

// shift op: x[32, 288, 64, 64] f32, NCHW. cpg = 32.
// group g in 0..7: out[:, g*32+(0..31), h, w] = x[same ch, h+dh, w+dw] (0 outside)
// group 8 (c in [256,288)): zeros.
//
// One block = one (b,c) plane (64x64). 128 threads; thread owns one 32-byte
// oct (8 floats) in rows {r, r+16, r+32, r+48}. All global accesses are
// 256-bit (v8.b32) — sm_103 LDG.E.256/STG.E.256 — halving the memory
// instruction count and L1 wavefront pressure vs the float4 version.
// dw=+/-1 octs are rebuilt from the aligned oct + one shuffled element.

#define SH_H 64
#define SH_W 64
#define SH_C 288

__constant__ int c_dh[8] = {-1,  1,  0,  0, -1, -1,  1,  1};
__constant__ int c_dw[8] = { 0,  0, -1,  1, -1,  1, -1,  1};

struct F8 { float a[8]; };

__device__ __forceinline__ F8 ldg256(const float* p) {
    F8 v;
    asm volatile("ld.global.nc.v8.b32 {%0,%1,%2,%3,%4,%5,%6,%7}, [%8];"
                 : "=f"(v.a[0]), "=f"(v.a[1]), "=f"(v.a[2]), "=f"(v.a[3]),
                   "=f"(v.a[4]), "=f"(v.a[5]), "=f"(v.a[6]), "=f"(v.a[7])
                 : "l"(p));
    return v;
}

__device__ __forceinline__ void stg256_cs(float* p, const F8& v) {
    asm volatile("st.global.cs.v8.b32 [%0], {%1,%2,%3,%4,%5,%6,%7,%8};"
                 :: "l"(p),
                    "f"(v.a[0]), "f"(v.a[1]), "f"(v.a[2]), "f"(v.a[3]),
                    "f"(v.a[4]), "f"(v.a[5]), "f"(v.a[6]), "f"(v.a[7])
                 : "memory");
}

__global__ __launch_bounds__(128) void shift_kernel(const float* __restrict__ x,
                                                    float* __restrict__ out) {
    const int tid = threadIdx.x;
    const int wo  = tid & 7;          // oct index within row (0..7), 8 floats each
    const int r   = tid >> 3;         // 0..15; rows r + {0,16,32,48}

    const int bc = blockIdx.x;        // fused (b, c) plane index
    const int c  = bc - (bc / SH_C) * SH_C;
    const int g  = c >> 5;            // cpg = 32

    const long plane = (long)bc * (SH_H * SH_W);
    float* __restrict__ dbase = out + plane + wo * 8;

    F8 zero;
#pragma unroll
    for (int k = 0; k < 8; ++k) zero.a[k] = 0.f;

    if (g >= 8) {                     // zero group (channels 256..287)
#pragma unroll
        for (int i = 0; i < 4; ++i)
            stg256_cs(dbase + (r + (i << 4)) * SH_W, zero);
        return;
    }

    const int dh = c_dh[g];
    const int dw = c_dw[g];
    const float* __restrict__ sbase = x + plane + wo * 8;

    // Issue all 4 aligned 256-bit loads first (4 x 32B in flight per thread).
    F8 q[4];
#pragma unroll
    for (int i = 0; i < 4; ++i) {
        const int hs = r + (i << 4) + dh;
        q[i] = ((unsigned)hs < SH_H) ? ldg256(sbase + hs * SH_W) : zero;
    }

    if (dw == 0) {
#pragma unroll
        for (int i = 0; i < 4; ++i)
            stg256_cs(dbase + (r + (i << 4)) * SH_W, q[i]);
    } else if (dw > 0) {
        // out oct = {q[1..7], next_lane.q[0]}; wo==7 -> last elem = 0 (w=63)
#pragma unroll
        for (int i = 0; i < 4; ++i) {
            float nx = __shfl_down_sync(0xffffffffu, q[i].a[0], 1);
            if (wo == 7) nx = 0.f;
            F8 o;
#pragma unroll
            for (int k = 0; k < 7; ++k) o.a[k] = q[i].a[k + 1];
            o.a[7] = nx;
            stg256_cs(dbase + (r + (i << 4)) * SH_W, o);
        }
    } else {
        // out oct = {prev_lane.q[7], q[0..6]}; wo==0 -> first elem = 0 (w=0)
#pragma unroll
        for (int i = 0; i < 4; ++i) {
            float pw = __shfl_up_sync(0xffffffffu, q[i].a[7], 1);
            if (wo == 0) pw = 0.f;
            F8 o;
            o.a[0] = pw;
#pragma unroll
            for (int k = 1; k < 8; ++k) o.a[k] = q[i].a[k - 1];
            stg256_cs(dbase + (r + (i << 4)) * SH_W, o);
        }
    }
}

extern "C" void kernel_launch(void* const* d_in, const int* in_sizes, int n_in,
                              void* d_out, int out_size) {
    const float* x = (const float*)d_in[0];
    float* out = (float*)d_out;
    const int grid = 32 * SH_C;   // one block per (b, c) plane
    shift_kernel<<<grid, 128>>>(x, out);
}

// round 6
// speedup vs baseline: 1.0014x; 1.0014x over previous
#include <cuda_runtime.h>

// shift op: x[32, 288, 64, 64] f32, NCHW. cpg = 32.
// group g in 0..7: out[:, g*32+(0..31), h, w] = x[same ch, h+dh, w+dw] (0 outside)
// group 8 (c in [256,288)): zeros.
//
// One block = one (b,c) plane (64x64). 256 threads, each thread handles 4
// aligned float4 quads at rows {r, r+16, r+32, r+48}. dw=+/-1 quads rebuilt
// via lane shuffles, so every load is an aligned LDG.128 and each input byte
// is read exactly once.
//
// Stores use DEFAULT cache policy (no .cs): evict-normal lets the L2
// writeback coalescer batch dirty output lines into longer DRAM write
// bursts, which matters on this turnaround-limited mixed R/W stream.

#define SH_H 64
#define SH_W 64
#define SH_C 288

__constant__ int c_dh[8] = {-1,  1,  0,  0, -1, -1,  1,  1};
__constant__ int c_dw[8] = { 0,  0, -1,  1, -1,  1, -1,  1};

__global__ __launch_bounds__(256) void shift_kernel(const float* __restrict__ x,
                                                    float* __restrict__ out) {
    const int tid   = threadIdx.x;
    const int wq    = tid & 15;        // quad index within row (0..15)
    const int rbase = tid >> 4;        // 0..15; rows rbase + {0,16,32,48}

    const int bc = blockIdx.x;         // fused (b, c) plane index
    const int c  = bc - (bc / SH_C) * SH_C;
    const int g  = c >> 5;             // cpg = 32

    const long plane = (long)bc * (SH_H * SH_W);
    float4* __restrict__ dstp = reinterpret_cast<float4*>(out + plane) + wq;

    const float4 zero = make_float4(0.f, 0.f, 0.f, 0.f);

    if (g >= 8) {                      // zero group (channels 256..287)
#pragma unroll
        for (int i = 0; i < 4; ++i) {
            const int h = rbase + (i << 4);
            dstp[h * (SH_W / 4)] = zero;
        }
        return;
    }

    const int dh = c_dh[g];
    const int dw = c_dw[g];

    const float4* __restrict__ srcp = reinterpret_cast<const float4*>(x + plane) + wq;

    // Issue all 4 aligned loads first (MLP=4). OOB source rows -> zero quad.
    float4 q[4];
#pragma unroll
    for (int i = 0; i < 4; ++i) {
        const int hs = rbase + (i << 4) + dh;
        q[i] = ((unsigned)hs < SH_H) ? __ldg(srcp + hs * (SH_W / 4)) : zero;
    }

    if (dw == 0) {
#pragma unroll
        for (int i = 0; i < 4; ++i) {
            const int h = rbase + (i << 4);
            dstp[h * (SH_W / 4)] = q[i];
        }
    } else if (dw > 0) {
        // out quad = {q.y, q.z, q.w, next_lane.q.x}; wq==15 -> last elem = 0
#pragma unroll
        for (int i = 0; i < 4; ++i) {
            float nx = __shfl_down_sync(0xffffffffu, q[i].x, 1);
            if (wq == 15) nx = 0.f;
            const int h = rbase + (i << 4);
            dstp[h * (SH_W / 4)] = make_float4(q[i].y, q[i].z, q[i].w, nx);
        }
    } else {
        // out quad = {prev_lane.q.w, q.x, q.y, q.z}; wq==0 -> first elem = 0
#pragma unroll
        for (int i = 0; i < 4; ++i) {
            float pw = __shfl_up_sync(0xffffffffu, q[i].w, 1);
            if (wq == 0) pw = 0.f;
            const int h = rbase + (i << 4);
            dstp[h * (SH_W / 4)] = make_float4(pw, q[i].x, q[i].y, q[i].z);
        }
    }
}

extern "C" void kernel_launch(void* const* d_in, const int* in_sizes, int n_in,
                              void* d_out, int out_size) {
    const float* x = (const float*)d_in[0];
    float* out = (float*)d_out;
    const int grid = 32 * SH_C;   // one block per (b, c) plane
    shift_kernel<<<grid, 256>>>(x, out);
}